// round 2
// baseline (speedup 1.0000x reference)
#include <cuda_runtime.h>
#include <cstdint>

// Problem constants (DeformConvPack_39187281609181)
#define B_   4
#define C_   64
#define H_   128
#define W_   256
#define HW_  (H_ * W_)      // 32768
#define COUT 64
#define KK   9              // 3x3
#define HO   128
#define WO   256
#define NPIX (B_ * HO * WO) // 131072

#define THREADS 256
#define SMEM_W_FLOATS (KK * C_ * COUT)     // 36864
#define SMEM_BYTES    (SMEM_W_FLOATS * 4)  // 147456

__global__ void __launch_bounds__(THREADS, 1)
deform_conv_kernel(const float* __restrict__ x,
                   const float* __restrict__ offset,
                   const float* __restrict__ weight,
                   const float* __restrict__ bias,
                   float* __restrict__ out)
{
    extern __shared__ float w_s[];   // layout: [(k*64 + c)*64 + oc]

    const int tid = threadIdx.x;

    // ---- Stage weights into smem, transposed (Cout,Cin,3,3) -> [k][c][oc] ----
    // src index: oc*576 + c*9 + k ; dst index t = (k*64+c)*64 + oc (contiguous store)
    for (int t = tid; t < SMEM_W_FLOATS; t += THREADS) {
        int oc = t & 63;
        int ck = t >> 6;        // k*64 + c
        int k  = ck >> 6;       // 0..8
        int c  = ck & 63;
        w_s[t] = __ldg(weight + oc * (C_ * KK) + c * KK + k);
    }

    // ---- Accumulators: 32 packed f32x2 covering oc = (2i, 2i+1), init = bias ----
    unsigned long long acc[32];
    {
        const float2* b2 = reinterpret_cast<const float2*>(bias);
        #pragma unroll
        for (int i = 0; i < 32; ++i) {
            float2 t = __ldg(b2 + i);
            asm("mov.b64 %0, {%1, %2};" : "=l"(acc[i]) : "f"(t.x), "f"(t.y));
        }
    }

    __syncthreads();

    // ---- Pixel assignment ----
    const int p  = blockIdx.x * THREADS + tid;   // 0..131071
    const int b  = p >> 15;                      // / (HO*WO)
    const int hw = p & 32767;
    const int ho = hw >> 8;                      // / WO
    const int wo = hw & 255;

    const float* xb = x + (size_t)b * C_ * HW_;

    #pragma unroll 1
    for (int k = 0; k < KK; ++k) {
        const int ky = k / 3;
        const int kx = k - 3 * ky;

        // offsets: (B, 2K, Ho, Wo), dy = chan 2k, dx = chan 2k+1
        const size_t obase = (((size_t)b * (2 * KK) + 2 * k) * HO + ho) * WO + wo;
        const float dy = __ldg(offset + obase);
        const float dx = __ldg(offset + obase + (size_t)HO * WO);

        const float py = (float)(ho - 1 + ky) + dy;
        const float px = (float)(wo - 1 + kx) + dx;

        const float y0f = floorf(py);
        const float x0f = floorf(px);
        const float ly = py - y0f;
        const float lx = px - x0f;

        const int y0 = (int)y0f;
        const int x0 = (int)x0f;
        const int y1 = y0 + 1;
        const int x1 = x0 + 1;

        const float vy0 = (y0 >= 0 && y0 < H_) ? 1.0f : 0.0f;
        const float vy1 = (y1 >= 0 && y1 < H_) ? 1.0f : 0.0f;
        const float vx0 = (x0 >= 0 && x0 < W_) ? 1.0f : 0.0f;
        const float vx1 = (x1 >= 0 && x1 < W_) ? 1.0f : 0.0f;

        const float w00 = (1.0f - ly) * (1.0f - lx) * vy0 * vx0;
        const float w01 = (1.0f - ly) * lx          * vy0 * vx1;
        const float w10 = ly          * (1.0f - lx) * vy1 * vx0;
        const float w11 = ly          * lx          * vy1 * vx1;

        const int y0c = min(max(y0, 0), H_ - 1);
        const int y1c = min(max(y1, 0), H_ - 1);
        const int x0c = min(max(x0, 0), W_ - 1);
        const int x1c = min(max(x1, 0), W_ - 1);

        const int s00 = y0c * W_ + x0c;
        const int s01 = y0c * W_ + x1c;
        const int s10 = y1c * W_ + x0c;
        const int s11 = y1c * W_ + x1c;

        const ulonglong2* wk =
            reinterpret_cast<const ulonglong2*>(w_s + k * (C_ * COUT));

        #pragma unroll 4
        for (int c = 0; c < C_; ++c) {
            const float* xc = xb + (size_t)c * HW_;
            const float v00 = __ldg(xc + s00);
            const float v01 = __ldg(xc + s01);
            const float v10 = __ldg(xc + s10);
            const float v11 = __ldg(xc + s11);

            float val = w00 * v00;
            val = fmaf(w01, v01, val);
            val = fmaf(w10, v10, val);
            val = fmaf(w11, v11, val);

            unsigned long long v2;
            asm("mov.b64 %0, {%1, %1};" : "=l"(v2) : "f"(val));

            const ulonglong2* wc = wk + c * 16;  // 64 floats = 16 x ulonglong2
            #pragma unroll
            for (int j = 0; j < 16; ++j) {
                ulonglong2 ww = wc[j];
                asm("fma.rn.f32x2 %0, %1, %2, %0;"
                    : "+l"(acc[2 * j])     : "l"(v2), "l"(ww.x));
                asm("fma.rn.f32x2 %0, %1, %2, %0;"
                    : "+l"(acc[2 * j + 1]) : "l"(v2), "l"(ww.y));
            }
        }
    }

    // ---- Epilogue: out(B, Cout, Ho, Wo) ----
    const size_t obase = (size_t)b * COUT * (HO * WO) + (size_t)ho * WO + wo;
    #pragma unroll
    for (int i = 0; i < 32; ++i) {
        float lo, hi;
        asm("mov.b64 {%0, %1}, %2;" : "=f"(lo), "=f"(hi) : "l"(acc[i]));
        out[obase + (size_t)(2 * i)     * (HO * WO)] = lo;
        out[obase + (size_t)(2 * i + 1) * (HO * WO)] = hi;
    }
}

extern "C" void kernel_launch(void* const* d_in, const int* in_sizes, int n_in,
                              void* d_out, int out_size)
{
    const float* x      = (const float*)d_in[0];
    const float* offset = (const float*)d_in[1];
    const float* weight = (const float*)d_in[2];
    const float* bias   = (const float*)d_in[3];
    float* out = (float*)d_out;

    cudaFuncSetAttribute(deform_conv_kernel,
                         cudaFuncAttributeMaxDynamicSharedMemorySize, SMEM_BYTES);

    deform_conv_kernel<<<NPIX / THREADS, THREADS, SMEM_BYTES>>>(
        x, offset, weight, bias, out);
}